// round 2
// baseline (speedup 1.0000x reference)
#include <cuda_runtime.h>
#include <cuda_bf16.h>
#include <cstdint>

// ---------------------------------------------------------------------------
// SyntaxGCN: GCNConv(512->256) + relu + global_mean_pool + linear(256->1) + sigmoid
//   Inputs (metadata order):
//     0: x        float32  [20000, 512]
//     1: edge_idx int32    [2, 320000]   (JAX x64 disabled -> int32!)
//     2: batch    int32    [20000]       (sorted graph ids, 0..255)
//     3: W        float32  [512, 256]
//     4: b        float32  [256]
//     5: lin_w    float32  [256, 1]
//     6: lin_b    float32  [1]
//   Output: float32 [256]
//
// Math factorization:
//   deg[n]  = 1 + #edges with dst==n
//   dinv[n] = rsqrt(deg[n])
//   hs[n]   = (x[n] @ W) * dinv[n]
//   acc[n]  = hs[n] + sum_{e: dst==n} hs[src_e]        (self loop folded in)
//   xr[n]   = relu(dinv[n]*acc[n] + b)
//   pooled[g] = sum_{batch[n]==g} xr[n];  counts[g] = #nodes in graph g
//   out[g]  = sigmoid( dot(pooled[g], lin_w)/max(counts[g],1) + lin_b )
// ---------------------------------------------------------------------------

constexpr int N_NODES  = 20000;
constexpr int N_EDGES  = 320000;
constexpr int IN_DIM   = 512;
constexpr int HID      = 256;
constexpr int HID4     = HID / 4;       // 64 float4 per row
constexpr int N_GRAPHS = 256;

// Scratch (device globals; float4 => guaranteed 16B alignment for red.v4)
__device__ float4 g_hs[N_NODES * HID4];
__device__ float4 g_acc[N_NODES * HID4];
__device__ float  g_dinv[N_NODES];
__device__ int    g_deg[N_NODES];
__device__ float4 g_pooled[N_GRAPHS * HID4];
__device__ float  g_counts[N_GRAPHS];

__device__ __forceinline__ void red_add_v4(float4* addr, float4 v) {
    asm volatile("red.global.add.v4.f32 [%0], {%1,%2,%3,%4};"
                 :: "l"(addr), "f"(v.x), "f"(v.y), "f"(v.z), "f"(v.w)
                 : "memory");
}

// --- init: pooled=0, counts=0, deg=1 ---------------------------------------
__global__ void init_kernel() {
    int i = blockIdx.x * blockDim.x + threadIdx.x;
    if (i < N_GRAPHS * HID4) g_pooled[i] = make_float4(0.f, 0.f, 0.f, 0.f);
    if (i < N_GRAPHS)        g_counts[i] = 0.f;
    if (i < N_NODES)         g_deg[i] = 1;
}

// --- degree count over dst --------------------------------------------------
__global__ void deg_kernel(const int* __restrict__ ei) {
    int e = blockIdx.x * blockDim.x + threadIdx.x;
    if (e < N_EDGES) {
        int dst = ei[N_EDGES + e];
        atomicAdd(&g_deg[dst], 1);
    }
}

// --- dinv = rsqrt(deg) ------------------------------------------------------
__global__ void dinv_kernel() {
    int n = blockIdx.x * blockDim.x + threadIdx.x;
    if (n < N_NODES) g_dinv[n] = rsqrtf((float)g_deg[n]);
}

// --- GEMM: hs = (x @ W) * dinv[row]; acc = hs (self-loop init) -------------
// 128x128 tile, TK=8, 256 threads, 8x8 per thread.
__global__ __launch_bounds__(256) void gemm_hs_kernel(
    const float* __restrict__ X, const float* __restrict__ W)
{
    __shared__ float As[8][128];
    __shared__ float Bs[8][128];
    const int tid = threadIdx.x;
    const int m0 = blockIdx.y * 128;
    const int n0 = blockIdx.x * 128;

    const int arow = tid >> 1, acol = (tid & 1) * 4;   // A: 128 rows x 8 k
    const int brow = tid >> 5, bcol = (tid & 31) * 4;  // B: 8 k x 128 cols
    const int ty = tid >> 4, tx = tid & 15;

    float accr[8][8];
    #pragma unroll
    for (int i = 0; i < 8; i++)
        #pragma unroll
        for (int j = 0; j < 8; j++) accr[i][j] = 0.f;

    const int aRowG = m0 + arow;
    const bool aValid = aRowG < N_NODES;
    const float* aPtr = X + (size_t)(aValid ? aRowG : 0) * IN_DIM + acol;
    const float* bPtr = W + (size_t)brow * HID + n0 + bcol;

    for (int k0 = 0; k0 < IN_DIM; k0 += 8) {
        float4 a = aValid ? *(const float4*)(aPtr + k0) : make_float4(0.f, 0.f, 0.f, 0.f);
        As[acol + 0][arow] = a.x;
        As[acol + 1][arow] = a.y;
        As[acol + 2][arow] = a.z;
        As[acol + 3][arow] = a.w;
        *(float4*)&Bs[brow][bcol] = *(const float4*)(bPtr + (size_t)k0 * HID);
        __syncthreads();

        #pragma unroll
        for (int kk = 0; kk < 8; kk++) {
            float4 a0 = *(const float4*)&As[kk][ty * 8];
            float4 a1 = *(const float4*)&As[kk][ty * 8 + 4];
            float4 b0 = *(const float4*)&Bs[kk][tx * 8];
            float4 b1 = *(const float4*)&Bs[kk][tx * 8 + 4];
            float ar[8] = {a0.x, a0.y, a0.z, a0.w, a1.x, a1.y, a1.z, a1.w};
            float br[8] = {b0.x, b0.y, b0.z, b0.w, b1.x, b1.y, b1.z, b1.w};
            #pragma unroll
            for (int i = 0; i < 8; i++)
                #pragma unroll
                for (int j = 0; j < 8; j++)
                    accr[i][j] += ar[i] * br[j];
        }
        __syncthreads();
    }

    #pragma unroll
    for (int i = 0; i < 8; i++) {
        int row = m0 + ty * 8 + i;
        if (row < N_NODES) {
            float d = g_dinv[row];
            int col4 = (n0 >> 2) + tx * 2;          // float4 column index
            float4 v0 = make_float4(accr[i][0] * d, accr[i][1] * d,
                                    accr[i][2] * d, accr[i][3] * d);
            float4 v1 = make_float4(accr[i][4] * d, accr[i][5] * d,
                                    accr[i][6] * d, accr[i][7] * d);
            size_t off = (size_t)row * HID4 + col4;
            g_hs[off]      = v0;
            g_hs[off + 1]  = v1;
            g_acc[off]     = v0;
            g_acc[off + 1] = v1;
        }
    }
}

// --- edge scatter: acc[dst] += hs[src], 64 float4 lanes per edge ------------
__global__ __launch_bounds__(256) void edge_scatter_kernel(const int* __restrict__ ei) {
    int t = blockIdx.x * blockDim.x + threadIdx.x;
    int e = t >> 6;
    int lane = t & 63;
    if (e >= N_EDGES) return;
    int src = __ldg(&ei[e]);
    int dst = __ldg(&ei[N_EDGES + e]);
    float4 v = __ldg(&g_hs[(size_t)src * HID4 + lane]);
    red_add_v4(&g_acc[(size_t)dst * HID4 + lane], v);
}

// --- relu + pool: pooled[g] += relu(dinv[n]*acc[n] + b); counts[g] += 1 -----
__global__ __launch_bounds__(256) void pool_kernel(
    const int* __restrict__ batch, const float* __restrict__ b)
{
    int t = blockIdx.x * blockDim.x + threadIdx.x;
    int n = t >> 6;
    int lane = t & 63;
    if (n >= N_NODES) return;
    int g = __ldg(&batch[n]);
    float d = g_dinv[n];
    float4 a = g_acc[(size_t)n * HID4 + lane];
    float4 bb = __ldg((const float4*)b + lane);
    float4 v;
    v.x = fmaxf(fmaf(a.x, d, bb.x), 0.f);
    v.y = fmaxf(fmaf(a.y, d, bb.y), 0.f);
    v.z = fmaxf(fmaf(a.z, d, bb.z), 0.f);
    v.w = fmaxf(fmaf(a.w, d, bb.w), 0.f);
    red_add_v4(&g_pooled[(size_t)g * HID4 + lane], v);
    if (lane == 0) atomicAdd(&g_counts[g], 1.f);
}

// --- head: out[g] = sigmoid( dot(pooled[g], lin_w)/max(cnt,1) + lin_b ) -----
__global__ void head_kernel(
    const float* __restrict__ lin_w, const float* __restrict__ lin_b,
    float* __restrict__ out)
{
    __shared__ float red[256];
    int g = blockIdx.x;
    int t = threadIdx.x;
    const float* pooled = (const float*)g_pooled;
    float v = pooled[g * HID + t] * __ldg(&lin_w[t]);
    red[t] = v;
    __syncthreads();
    #pragma unroll
    for (int s = 128; s > 0; s >>= 1) {
        if (t < s) red[t] += red[t + s];
        __syncthreads();
    }
    if (t == 0) {
        float cnt = fmaxf(g_counts[g], 1.f);
        float z = red[0] / cnt + __ldg(&lin_b[0]);
        out[g] = 1.f / (1.f + expf(-z));
    }
}

// ---------------------------------------------------------------------------
extern "C" void kernel_launch(void* const* d_in, const int* in_sizes, int n_in,
                              void* d_out, int out_size) {
    const float* x     = (const float*)d_in[0];
    const int*   ei    = (const int*)d_in[1];     // int32 (JAX default)
    const int*   batch = (const int*)d_in[2];     // int32
    const float* W     = (const float*)d_in[3];
    const float* b     = (const float*)d_in[4];
    const float* lin_w = (const float*)d_in[5];
    const float* lin_b = (const float*)d_in[6];
    float*       out   = (float*)d_out;

    init_kernel<<<(N_GRAPHS * HID + 255) / 256, 256>>>();
    deg_kernel<<<(N_EDGES + 255) / 256, 256>>>(ei);
    dinv_kernel<<<(N_NODES + 255) / 256, 256>>>();
    gemm_hs_kernel<<<dim3(HID / 128, (N_NODES + 127) / 128), 256>>>(x, W);
    edge_scatter_kernel<<<(N_EDGES * 64) / 256, 256>>>(ei);
    pool_kernel<<<(N_NODES * 64 + 255) / 256, 256>>>(batch, b);
    head_kernel<<<N_GRAPHS, 256>>>(lin_w, lin_b, out);
}

// round 4
// speedup vs baseline: 1.5919x; 1.5919x over previous
#include <cuda_runtime.h>
#include <cuda_bf16.h>
#include <cstdint>
#include <cstring>

// ---------------------------------------------------------------------------
// SyntaxGCN: GCNConv(512->256) + relu + global_mean_pool + linear(256->1) + sigmoid
// GEMM on tensor cores via portable mma.sync (HMMA) with bf16x2 split:
//   x*W ~= xh*Wh + xh*Wl + xl*Wh   (fp32 accumulate, rel err ~1e-5)
// (tcgen05 is unavailable: harness compiles PTX at compute_103, not 103a.)
// ---------------------------------------------------------------------------

constexpr int N_NODES  = 20000;
constexpr int N_EDGES  = 320000;
constexpr int IN_DIM   = 512;
constexpr int HID      = 256;
constexpr int HID4     = HID / 4;
constexpr int N_GRAPHS = 256;

constexpr int TILE_M = 128;
constexpr int TILE_N = 128;
constexpr int TK     = 32;                 // k per chunk
constexpr int NCHUNK = IN_DIM / TK;        // 16
constexpr int SSTR   = 40;                 // smem row stride in bf16 (80B: 16B-aligned, conflict-free)

// Scratch (device globals; float4 => 16B alignment for red.v4)
__device__ float4 g_hs[N_NODES * HID4];
__device__ float4 g_acc[N_NODES * HID4];
__device__ float  g_dinv[N_NODES];
__device__ int    g_deg[N_NODES];
__device__ float4 g_pooled[N_GRAPHS * HID4];
__device__ float  g_counts[N_GRAPHS];

// ---------------- helpers ---------------------------------------------------
__device__ __forceinline__ void red_add_v4(float4* addr, float4 v) {
    asm volatile("red.global.add.v4.f32 [%0], {%1,%2,%3,%4};"
                 :: "l"(addr), "f"(v.x), "f"(v.y), "f"(v.z), "f"(v.w)
                 : "memory");
}

__device__ __forceinline__ uint32_t pack_bf16x2(float a, float b) {
    __nv_bfloat162 h2 = __floats2bfloat162_rn(a, b);
    uint32_t u; memcpy(&u, &h2, 4);
    return u;
}

// split 2 floats into hi bf16x2 and lo (residual) bf16x2
__device__ __forceinline__ void split2(float v0, float v1, uint32_t& hi, uint32_t& lo) {
    __nv_bfloat16 h0 = __float2bfloat16_rn(v0);
    __nv_bfloat16 h1 = __float2bfloat16_rn(v1);
    hi = pack_bf16x2(v0, v1);
    lo = pack_bf16x2(v0 - __bfloat162float(h0), v1 - __bfloat162float(h1));
}

__device__ __forceinline__ void mma_bf16(float* c, const uint32_t* a,
                                         uint32_t b0, uint32_t b1) {
    asm volatile(
        "mma.sync.aligned.m16n8k16.row.col.f32.bf16.bf16.f32 "
        "{%0,%1,%2,%3}, {%4,%5,%6,%7}, {%8,%9}, {%0,%1,%2,%3};"
        : "+f"(c[0]), "+f"(c[1]), "+f"(c[2]), "+f"(c[3])
        : "r"(a[0]), "r"(a[1]), "r"(a[2]), "r"(a[3]), "r"(b0), "r"(b1));
}

__device__ __forceinline__ uint32_t lds_u32(const __nv_bfloat16* p) {
    return *reinterpret_cast<const uint32_t*>(p);
}

// --- init: pooled=0, counts=0, deg=1 ---------------------------------------
__global__ void init_kernel() {
    int i = blockIdx.x * blockDim.x + threadIdx.x;
    if (i < N_GRAPHS * HID4) g_pooled[i] = make_float4(0.f, 0.f, 0.f, 0.f);
    if (i < N_GRAPHS)        g_counts[i] = 0.f;
    if (i < N_NODES)         g_deg[i] = 1;
}

__global__ void deg_kernel(const int* __restrict__ ei) {
    int e = blockIdx.x * blockDim.x + threadIdx.x;
    if (e < N_EDGES) atomicAdd(&g_deg[ei[N_EDGES + e]], 1);
}

__global__ void dinv_kernel() {
    int n = blockIdx.x * blockDim.x + threadIdx.x;
    if (n < N_NODES) g_dinv[n] = rsqrtf((float)g_deg[n]);
}

// --- tensor-core GEMM: hs = (x @ W) * dinv[row]; acc = hs -------------------
// 256 threads, 8 warps (4 x 2), warp tile 32x64, mma m16n8k16 bf16.
__global__ __launch_bounds__(256, 2) void gemm_mma_kernel(
    const float* __restrict__ X, const float* __restrict__ W)
{
    __shared__ __nv_bfloat16 sAhi[TILE_M * SSTR];
    __shared__ __nv_bfloat16 sAlo[TILE_M * SSTR];
    __shared__ __nv_bfloat16 sBhi[TILE_N * SSTR];
    __shared__ __nv_bfloat16 sBlo[TILE_N * SSTR];

    const int tid  = threadIdx.x;
    const int lane = tid & 31;
    const int wid  = tid >> 5;
    const int warp_m = wid & 3;     // 4 warps over M (32 rows each)
    const int warp_n = wid >> 2;    // 2 warps over N (64 cols each)
    const int quad  = lane >> 2;    // 0..7
    const int tig   = lane & 3;     // 0..3

    const int m0 = blockIdx.y * TILE_M;
    const int n0 = blockIdx.x * TILE_N;

    float acc[2][8][4];
    #pragma unroll
    for (int i = 0; i < 2; i++)
        #pragma unroll
        for (int j = 0; j < 8; j++)
            #pragma unroll
            for (int c = 0; c < 4; c++) acc[i][j][c] = 0.f;

    // A-load mapping: 2 threads per row, 16 k each
    const int arow  = tid >> 1;
    const int ahalf = tid & 1;
    const bool aValid = (m0 + arow) < N_NODES;
    const float* aPtr = X + (size_t)(aValid ? m0 + arow : 0) * IN_DIM + ahalf * 16;
    // B-load mapping: thread covers one n, 16 k
    const int bn    = tid & 127;
    const int bhalf = tid >> 7;

    for (int chunk = 0; chunk < NCHUNK; chunk++) {
        const int k0 = chunk * TK;
        // ---- A: x[row][k0..k0+31] -> bf16 hi/lo ----
        {
            float f[16];
            if (aValid) {
                #pragma unroll
                for (int q = 0; q < 4; q++)
                    *(float4*)&f[q * 4] = *(const float4*)(aPtr + k0 + q * 4);
            } else {
                #pragma unroll
                for (int q = 0; q < 16; q++) f[q] = 0.f;
            }
            uint4 hv0, hv1, lv0, lv1;
            split2(f[0],  f[1],  hv0.x, lv0.x);
            split2(f[2],  f[3],  hv0.y, lv0.y);
            split2(f[4],  f[5],  hv0.z, lv0.z);
            split2(f[6],  f[7],  hv0.w, lv0.w);
            split2(f[8],  f[9],  hv1.x, lv1.x);
            split2(f[10], f[11], hv1.y, lv1.y);
            split2(f[12], f[13], hv1.z, lv1.z);
            split2(f[14], f[15], hv1.w, lv1.w);
            int e = arow * SSTR + ahalf * 16;
            *(uint4*)&sAhi[e]     = hv0;  *(uint4*)&sAhi[e + 8] = hv1;
            *(uint4*)&sAlo[e]     = lv0;  *(uint4*)&sAlo[e + 8] = lv1;
        }
        // ---- B: Bt[n][k] = W[k][n0+n] -> bf16 hi/lo ----
        {
            float f[16];
            const float* wPtr = W + (size_t)(k0 + bhalf * 16) * HID + n0 + bn;
            #pragma unroll
            for (int q = 0; q < 16; q++) f[q] = wPtr[(size_t)q * HID];
            uint4 hv0, hv1, lv0, lv1;
            split2(f[0],  f[1],  hv0.x, lv0.x);
            split2(f[2],  f[3],  hv0.y, lv0.y);
            split2(f[4],  f[5],  hv0.z, lv0.z);
            split2(f[6],  f[7],  hv0.w, lv0.w);
            split2(f[8],  f[9],  hv1.x, lv1.x);
            split2(f[10], f[11], hv1.y, lv1.y);
            split2(f[12], f[13], hv1.z, lv1.z);
            split2(f[14], f[15], hv1.w, lv1.w);
            int e = bn * SSTR + bhalf * 16;
            *(uint4*)&sBhi[e]     = hv0;  *(uint4*)&sBhi[e + 8] = hv1;
            *(uint4*)&sBlo[e]     = lv0;  *(uint4*)&sBlo[e + 8] = lv1;
        }
        __syncthreads();

        #pragma unroll
        for (int ks = 0; ks < 2; ks++) {
            const int kb = ks * 16;
            #pragma unroll
            for (int i = 0; i < 2; i++) {
                const int ra = (warp_m * 32 + i * 16 + quad) * SSTR + kb + tig * 2;
                uint32_t ahi[4], alo[4];
                ahi[0] = lds_u32(&sAhi[ra]);
                ahi[1] = lds_u32(&sAhi[ra + 8 * SSTR]);
                ahi[2] = lds_u32(&sAhi[ra + 8]);
                ahi[3] = lds_u32(&sAhi[ra + 8 * SSTR + 8]);
                alo[0] = lds_u32(&sAlo[ra]);
                alo[1] = lds_u32(&sAlo[ra + 8 * SSTR]);
                alo[2] = lds_u32(&sAlo[ra + 8]);
                alo[3] = lds_u32(&sAlo[ra + 8 * SSTR + 8]);
                #pragma unroll
                for (int j = 0; j < 8; j++) {
                    const int rb = (warp_n * 64 + j * 8 + quad) * SSTR + kb + tig * 2;
                    uint32_t bhi0 = lds_u32(&sBhi[rb]);
                    uint32_t bhi1 = lds_u32(&sBhi[rb + 8]);
                    uint32_t blo0 = lds_u32(&sBlo[rb]);
                    uint32_t blo1 = lds_u32(&sBlo[rb + 8]);
                    mma_bf16(acc[i][j], ahi, bhi0, bhi1);   // xh*Wh
                    mma_bf16(acc[i][j], ahi, blo0, blo1);   // xh*Wl
                    mma_bf16(acc[i][j], alo, bhi0, bhi1);   // xl*Wh
                }
            }
        }
        __syncthreads();
    }

    // ---- epilogue: scale by dinv, store hs & acc -------------------------
    #pragma unroll
    for (int i = 0; i < 2; i++) {
        const int r0 = m0 + warp_m * 32 + i * 16 + quad;
        const int r1 = r0 + 8;
        const bool v0 = r0 < N_NODES;
        const bool v1 = r1 < N_NODES;
        const float d0 = v0 ? g_dinv[r0] : 0.f;
        const float d1 = v1 ? g_dinv[r1] : 0.f;
        #pragma unroll
        for (int j = 0; j < 8; j++) {
            const int col = n0 + warp_n * 64 + j * 8 + tig * 2;
            if (v0) {
                float2 s = make_float2(acc[i][j][0] * d0, acc[i][j][1] * d0);
                *(float2*)((float*)g_hs  + (size_t)r0 * HID + col) = s;
                *(float2*)((float*)g_acc + (size_t)r0 * HID + col) = s;
            }
            if (v1) {
                float2 s = make_float2(acc[i][j][2] * d1, acc[i][j][3] * d1);
                *(float2*)((float*)g_hs  + (size_t)r1 * HID + col) = s;
                *(float2*)((float*)g_acc + (size_t)r1 * HID + col) = s;
            }
        }
    }
}

// --- edge scatter: acc[dst] += hs[src], 64 float4 lanes per edge ------------
__global__ __launch_bounds__(256) void edge_scatter_kernel(const int* __restrict__ ei) {
    int t = blockIdx.x * blockDim.x + threadIdx.x;
    int e = t >> 6;
    int lane = t & 63;
    if (e >= N_EDGES) return;
    int src = __ldg(&ei[e]);
    int dst = __ldg(&ei[N_EDGES + e]);
    float4 v = __ldg(&g_hs[(size_t)src * HID4 + lane]);
    red_add_v4(&g_acc[(size_t)dst * HID4 + lane], v);
}

// --- relu + pool -------------------------------------------------------------
__global__ __launch_bounds__(256) void pool_kernel(
    const int* __restrict__ batch, const float* __restrict__ b)
{
    int t = blockIdx.x * blockDim.x + threadIdx.x;
    int n = t >> 6;
    int lane = t & 63;
    if (n >= N_NODES) return;
    int g = __ldg(&batch[n]);
    float d = g_dinv[n];
    float4 a = g_acc[(size_t)n * HID4 + lane];
    float4 bb = __ldg((const float4*)b + lane);
    float4 v;
    v.x = fmaxf(fmaf(a.x, d, bb.x), 0.f);
    v.y = fmaxf(fmaf(a.y, d, bb.y), 0.f);
    v.z = fmaxf(fmaf(a.z, d, bb.z), 0.f);
    v.w = fmaxf(fmaf(a.w, d, bb.w), 0.f);
    red_add_v4(&g_pooled[(size_t)g * HID4 + lane], v);
    if (lane == 0) atomicAdd(&g_counts[g], 1.f);
}

// --- head --------------------------------------------------------------------
__global__ void head_kernel(
    const float* __restrict__ lin_w, const float* __restrict__ lin_b,
    float* __restrict__ out)
{
    __shared__ float red[256];
    int g = blockIdx.x;
    int t = threadIdx.x;
    const float* pooled = (const float*)g_pooled;
    red[t] = pooled[g * HID + t] * __ldg(&lin_w[t]);
    __syncthreads();
    #pragma unroll
    for (int s = 128; s > 0; s >>= 1) {
        if (t < s) red[t] += red[t + s];
        __syncthreads();
    }
    if (t == 0) {
        float cnt = fmaxf(g_counts[g], 1.f);
        float z = red[0] / cnt + __ldg(&lin_b[0]);
        out[g] = 1.f / (1.f + expf(-z));
    }
}

// ---------------------------------------------------------------------------
extern "C" void kernel_launch(void* const* d_in, const int* in_sizes, int n_in,
                              void* d_out, int out_size) {
    const float* x     = (const float*)d_in[0];
    const int*   ei    = (const int*)d_in[1];
    const int*   batch = (const int*)d_in[2];
    const float* W     = (const float*)d_in[3];
    const float* b     = (const float*)d_in[4];
    const float* lin_w = (const float*)d_in[5];
    const float* lin_b = (const float*)d_in[6];
    float*       out   = (float*)d_out;

    init_kernel<<<(N_GRAPHS * HID + 255) / 256, 256>>>();
    deg_kernel<<<(N_EDGES + 255) / 256, 256>>>(ei);
    dinv_kernel<<<(N_NODES + 255) / 256, 256>>>();
    gemm_mma_kernel<<<dim3(HID / TILE_N, (N_NODES + TILE_M - 1) / TILE_M), 256>>>(x, W);
    edge_scatter_kernel<<<(N_EDGES * 64) / 256, 256>>>(ei);
    pool_kernel<<<(N_NODES * 64 + 255) / 256, 256>>>(batch, b);
    head_kernel<<<N_GRAPHS, 256>>>(lin_w, lin_b, out);
}